// round 6
// baseline (speedup 1.0000x reference)
#include <cuda_runtime.h>
#include <math.h>

// Problem constants
#define NBATCH 8
#define NPTS   2048
#define NFEAT  32
#define NROWS  (NBATCH * NPTS)                       // 16384
#define NMAT   ((size_t)NBATCH * NPTS * NPTS)        // 33554432
#define MAX_IT 100
#define RB     16                                    // rows per iter block
#define RBLK   (NPTS / RB)                           // 128 row-blocks per batch

// eps = 0.1 ; log2-domain scale: (1/eps) * log2(e)
#define S2   14.4269504088896341f
#define LN2  0.6931471805599453f
#define EPSV 0.1f
#define LOG_MUV (logf(1.0f / 2048.0f + 1e-8f))
#define LOG_NUV LOG_MUV
#define ERR_THRESH_SUM 0.8f

// dynamic smem: v*S2 (2048 floats) + t tile (8 rows x 2048 = 16384 floats)
#define DYN_SMEM_BYTES ((NPTS + 8 * NPTS) * 4)       // 73728

// Scratch (__device__ globals; no allocation allowed)
__device__ __align__(16) float g_u[NROWS];
__device__ __align__(16) float g_v[NROWS];
__device__ float g_err[MAX_IT];
__device__ __align__(16) float g_pl[NBATCH * RBLK * NPTS];   // 8 MB col partial lse (log2)
__device__ __align__(16) float g_pl2[NBATCH * 8 * NPTS];     // stage-2 partials

__device__ __forceinline__ float ex2f(float x) {
    float y;
    asm("ex2.approx.ftz.f32 %0, %1;" : "=f"(y) : "f"(x));
    return y;
}
__device__ __forceinline__ float lg2f(float x) {
    float y;
    asm("lg2.approx.ftz.f32 %0, %1;" : "=f"(y) : "f"(x));
    return y;
}

// ---------------------------------------------------------------------------
// Init
// ---------------------------------------------------------------------------
__global__ void k_init(float* __restrict__ cost) {
    int t = blockIdx.x * blockDim.x + threadIdx.x;
    int n = gridDim.x * blockDim.x;
    for (int i = t; i < NROWS; i += n) {
        g_u[i] = 0.0f;
        g_v[i] = 0.0f;
    }
    if (t < MAX_IT) g_err[t] = 0.0f;
    if (t < NBATCH) cost[t] = 0.0f;
}

// ---------------------------------------------------------------------------
// Cost matrix: C[b,i,j] = sum_d (x[b,i,d] - y[b,j,d])^2
// ---------------------------------------------------------------------------
__global__ void __launch_bounds__(256) k_cost(const float* __restrict__ x,
                                              const float* __restrict__ y,
                                              float* __restrict__ C) {
    __shared__ float xs[NFEAT * 65];
    __shared__ float ys[NFEAT * 65];

    int tile = blockIdx.x;          // 8192 tiles of 64x64
    int b  = tile >> 10;
    int ti = (tile >> 5) & 31;
    int tj = tile & 31;
    int tid = threadIdx.x;

    const float* xb = x + ((size_t)b * NPTS + (size_t)ti * 64) * NFEAT;
    const float* yb = y + ((size_t)b * NPTS + (size_t)tj * 64) * NFEAT;

    for (int e = tid; e < 64 * NFEAT; e += 256) {
        int row = e >> 5;
        int d   = e & 31;
        xs[d * 65 + row] = xb[e];
        ys[d * 65 + row] = yb[e];
    }
    __syncthreads();

    int ri = (tid >> 4) << 2;
    int cj = (tid & 15) << 2;

    float acc[4][4];
#pragma unroll
    for (int a = 0; a < 4; a++)
#pragma unroll
        for (int c = 0; c < 4; c++) acc[a][c] = 0.0f;

#pragma unroll
    for (int d = 0; d < NFEAT; d++) {
        float xa[4], yv[4];
#pragma unroll
        for (int a = 0; a < 4; a++) xa[a] = xs[d * 65 + ri + a];
#pragma unroll
        for (int c = 0; c < 4; c++) yv[c] = ys[d * 65 + cj + c];
#pragma unroll
        for (int a = 0; a < 4; a++)
#pragma unroll
            for (int c = 0; c < 4; c++) {
                float diff = xa[a] - yv[c];
                acc[a][c] = fmaf(diff, diff, acc[a][c]);
            }
    }

    float* Cb = C + (size_t)b * NPTS * NPTS + (size_t)(ti * 64 + ri) * NPTS + (tj * 64 + cj);
#pragma unroll
    for (int a = 0; a < 4; a++) {
        float4 o = make_float4(acc[a][0], acc[a][1], acc[a][2], acc[a][3]);
        *reinterpret_cast<float4*>(Cb + (size_t)a * NPTS) = o;
    }
}

// ---------------------------------------------------------------------------
// Fused iteration: 256 threads (8 warps), 16 rows, 2 chunks of 8 rows.
// Phase 1 (per chunk): warp w scans its full row (one row per warp),
//   t = (v - C)*S2 -> dynamic smem tile, dual-accumulator online LSE -> u_new.
// Phase 2 (per chunk): 512 float4-columns split across 256 threads x 2 halves;
//   each column folds its 8 rows in ONE grouped online-LSE step (9 ex2/8).
// Column partial stored as single log2-domain lse. 4 syncs per block.
// Early freeze: g_err[it-1] < thresh (sticky).
// ---------------------------------------------------------------------------
extern __shared__ float dyn_s[];

__global__ void __launch_bounds__(256, 3) k_iter(const float* __restrict__ C, int it) {
    if (it > 0 && g_err[it - 1] < ERR_THRESH_SUM) return;

    __shared__ float uS2_s[8];
    __shared__ float blkerr;

    float* vS2_s = dyn_s;                 // 2048 floats
    float* t_s   = dyn_s + NPTS;          // 8 * 2048 floats

    int blk = blockIdx.x;                 // 8 * 128 = 1024 blocks
    int b   = blk >> 7;
    int rb  = blk & 127;
    int tid = threadIdx.x;
    int w   = tid >> 5;
    int l   = tid & 31;

    const float4* vg  = reinterpret_cast<const float4*>(g_v + (b << 11));
    float4*       vs4 = reinterpret_cast<float4*>(vS2_s);
#pragma unroll
    for (int k = 0; k < 2; k++) {
        float4 t = vg[tid + (k << 8)];
        t.x *= S2; t.y *= S2; t.z *= S2; t.w *= S2;
        vs4[tid + (k << 8)] = t;
    }
    if (tid == 0) blkerr = 0.0f;
    __syncthreads();

    const float* Cb  = C + ((size_t)b << 22) + (((size_t)rb * RB) << 11);
    float4*      ts4 = reinterpret_cast<float4*>(t_s);

    // 8 column accumulators per thread: [half*4 + c], half in {0,1}
    float cm[8], cs[8];
#pragma unroll
    for (int q = 0; q < 8; q++) { cm[q] = -1e30f; cs[q] = 0.0f; }

#pragma unroll 1
    for (int ch = 0; ch < 2; ch++) {
        // ---- phase 1: warp w handles row rl = ch*8 + w ----
        {
            int rl = (ch << 3) + w;
            int r  = (b << 11) + rb * RB + rl;
            const float4* Cr   = reinterpret_cast<const float4*>(Cb + ((size_t)rl << 11));
            float4*       trow = ts4 + (w << 9);     // warp's 512-float4 slot

            float m0 = -1e30f, s0 = 0.0f, m1 = -1e30f, s1 = 0.0f;
#pragma unroll
            for (int g = 0; g < 8; g++) {
                int idx = l + (g << 6);
                float4 c0 = Cr[idx];
                float4 c1 = Cr[idx + 32];
                float4 v0 = vs4[idx];
                float4 v1 = vs4[idx + 32];
                float t0 = fmaf(-S2, c0.x, v0.x);
                float t1 = fmaf(-S2, c0.y, v0.y);
                float t2 = fmaf(-S2, c0.z, v0.z);
                float t3 = fmaf(-S2, c0.w, v0.w);
                float t4 = fmaf(-S2, c1.x, v1.x);
                float t5 = fmaf(-S2, c1.y, v1.y);
                float t6 = fmaf(-S2, c1.z, v1.z);
                float t7 = fmaf(-S2, c1.w, v1.w);
                trow[idx]      = make_float4(t0, t1, t2, t3);
                trow[idx + 32] = make_float4(t4, t5, t6, t7);
                // dual independent accumulators to shorten the rescale chain
                float mA = fmaxf(fmaxf(t0, t1), fmaxf(t2, t3));
                float n0 = fmaxf(m0, mA);
                s0 = s0 * ex2f(m0 - n0)
                   + ((ex2f(t0 - n0) + ex2f(t1 - n0)) + (ex2f(t2 - n0) + ex2f(t3 - n0)));
                m0 = n0;
                float mB = fmaxf(fmaxf(t4, t5), fmaxf(t6, t7));
                float n1 = fmaxf(m1, mB);
                s1 = s1 * ex2f(m1 - n1)
                   + ((ex2f(t4 - n1) + ex2f(t5 - n1)) + (ex2f(t6 - n1) + ex2f(t7 - n1)));
                m1 = n1;
            }
            float m = fmaxf(m0, m1);
            float s = s0 * ex2f(m0 - m) + s1 * ex2f(m1 - m);
#pragma unroll
            for (int o = 16; o; o >>= 1) {
                float mo = __shfl_xor_sync(0xffffffffu, m, o);
                float so = __shfl_xor_sync(0xffffffffu, s, o);
                float nm = fmaxf(m, mo);
                s = s * ex2f(m - nm) + so * ex2f(mo - nm);
                m = nm;
            }
            if (l == 0) {
                float lse  = (m + lg2f(s)) * LN2;    // natural-log lse of (v - C)/eps
                float unew = EPSV * (LOG_MUV - lse);
                float du = fabsf(unew - g_u[r]);
                g_u[r]   = unew;
                uS2_s[w] = unew * S2;
                atomicAdd(&blkerr, du);
            }
        }
        __syncthreads();   // t tile + uS2 ready

        // ---- phase 2: fold 8 rows per column, one grouped LSE step ----
        {
            float us[8];
#pragma unroll
            for (int r = 0; r < 8; r++) us[r] = uS2_s[r];

#pragma unroll
            for (int h = 0; h < 2; h++) {
                int cq = (h << 8) + tid;             // float4 column index
                float4 tr[8];
#pragma unroll
                for (int r = 0; r < 8; r++) tr[r] = ts4[(r << 9) + cq];
#define COLUPD8(q, E)                                                           \
                {                                                               \
                    float a0 = tr[0].E + us[0];                                 \
                    float a1 = tr[1].E + us[1];                                 \
                    float a2 = tr[2].E + us[2];                                 \
                    float a3 = tr[3].E + us[3];                                 \
                    float a4 = tr[4].E + us[4];                                 \
                    float a5 = tr[5].E + us[5];                                 \
                    float a6 = tr[6].E + us[6];                                 \
                    float a7 = tr[7].E + us[7];                                 \
                    float m8 = fmaxf(fmaxf(fmaxf(a0, a1), fmaxf(a2, a3)),      \
                                     fmaxf(fmaxf(a4, a5), fmaxf(a6, a7)));     \
                    float nm = fmaxf(cm[q], m8);                                \
                    cs[q] = cs[q] * ex2f(cm[q] - nm)                            \
                          + (((ex2f(a0 - nm) + ex2f(a1 - nm))                   \
                            + (ex2f(a2 - nm) + ex2f(a3 - nm)))                  \
                           + ((ex2f(a4 - nm) + ex2f(a5 - nm))                   \
                            + (ex2f(a6 - nm) + ex2f(a7 - nm))));                \
                    cm[q] = nm;                                                 \
                }
                COLUPD8((h << 2) + 0, x)
                COLUPD8((h << 2) + 1, y)
                COLUPD8((h << 2) + 2, z)
                COLUPD8((h << 2) + 3, w)
#undef COLUPD8
            }
        }
        __syncthreads();   // protect t tile before next chunk rewrites it
    }

    // write column partials (coalesced float4, log2-domain single float)
    float4* po = reinterpret_cast<float4*>(g_pl + ((size_t)blk << 11));
    po[tid]       = make_float4(cm[0] + lg2f(cs[0]), cm[1] + lg2f(cs[1]),
                                cm[2] + lg2f(cs[2]), cm[3] + lg2f(cs[3]));
    po[tid + 256] = make_float4(cm[4] + lg2f(cs[4]), cm[5] + lg2f(cs[5]),
                                cm[6] + lg2f(cs[6]), cm[7] + lg2f(cs[7]));
    if (tid == 0) atomicAdd(&g_err[it], blkerr);
}

// ---------------------------------------------------------------------------
// v reduce, stage A: merge 16 log2-domain partials -> 8 per column.
// ---------------------------------------------------------------------------
__global__ void __launch_bounds__(256) k_vredA(int it) {
    if (it > 0 && g_err[it - 1] < ERR_THRESH_SUM) return;
    int t   = blockIdx.x * 256 + threadIdx.x;    // 512 blocks -> 131072 threads
    int col = t & 2047;
    int pg  = (t >> 11) & 7;
    int b   = t >> 14;
    size_t base = (((size_t)(b * RBLK + pg * 16)) << 11) + col;
    float m0 = -1e30f, s0 = 0.0f, m1 = -1e30f, s1 = 0.0f;
#pragma unroll
    for (int k = 0; k < 16; k += 2) {
        float p0 = g_pl[base + ((size_t)k << 11)];
        float p1 = g_pl[base + ((size_t)(k + 1) << 11)];
        float n0 = fmaxf(m0, p0);
        s0 = s0 * ex2f(m0 - n0) + ex2f(p0 - n0);
        m0 = n0;
        float n1 = fmaxf(m1, p1);
        s1 = s1 * ex2f(m1 - n1) + ex2f(p1 - n1);
        m1 = n1;
    }
    float m = fmaxf(m0, m1);
    float s = s0 * ex2f(m0 - m) + s1 * ex2f(m1 - m);
    g_pl2[(((size_t)(b * 8 + pg)) << 11) + col] = m + lg2f(s);
}

// ---------------------------------------------------------------------------
// v reduce, stage B: merge 8 -> v_new = v_old + eps*(log_nu - lse).
// ---------------------------------------------------------------------------
__global__ void __launch_bounds__(256) k_vredB(int it) {
    if (it > 0 && g_err[it - 1] < ERR_THRESH_SUM) return;
    int t   = blockIdx.x * 256 + threadIdx.x;    // 64 blocks -> 16384 threads
    int col = t & 2047;
    int b   = t >> 11;
    size_t base = (((size_t)(b * 8)) << 11) + col;
    float m = -1e30f, s = 0.0f;
#pragma unroll
    for (int k = 0; k < 8; k++) {
        float p = g_pl2[base + ((size_t)k << 11)];
        float nm = fmaxf(m, p);
        s = s * ex2f(m - nm) + ex2f(p - nm);
        m = nm;
    }
    int j = (b << 11) + col;
    // lse already includes v (a = (u+v-C)*S2): v_new = v + eps*(log_nu - lse)
    g_v[j] = g_v[j] + EPSV * (LOG_NUV - (m + lg2f(s)) * LN2);
}

// ---------------------------------------------------------------------------
// Epilogue: pi = exp((u_i + v_j - C_ij)/eps), cost[b] = sum pi*C
// ---------------------------------------------------------------------------
__global__ void __launch_bounds__(256) k_pi(const float* __restrict__ C,
                                            float* __restrict__ pi,
                                            float* __restrict__ cost) {
    __shared__ float blkcost;
    if (threadIdx.x == 0) blkcost = 0.0f;
    __syncthreads();

    int warp = (blockIdx.x << 3) + (threadIdx.x >> 5);
    int lane = threadIdx.x & 31;
    int r = warp;
    int b = r >> 11;

    float u = g_u[r];
    const float4* Cr = reinterpret_cast<const float4*>(C + (size_t)r * NPTS);
    const float4* Vr = reinterpret_cast<const float4*>(g_v + (b << 11));
    float4* Pr = reinterpret_cast<float4*>(pi + (size_t)r * NPTS);

    float acc = 0.0f;
#pragma unroll 4
    for (int k = lane; k < NPTS / 4; k += 32) {
        float4 c = Cr[k];
        float4 v = Vr[k];
        float4 p;
        p.x = ex2f((u + v.x - c.x) * S2);
        p.y = ex2f((u + v.y - c.y) * S2);
        p.z = ex2f((u + v.z - c.z) * S2);
        p.w = ex2f((u + v.w - c.w) * S2);
        Pr[k] = p;
        acc += p.x * c.x + p.y * c.y + p.z * c.z + p.w * c.w;
    }
#pragma unroll
    for (int o = 16; o; o >>= 1) acc += __shfl_xor_sync(0xffffffffu, acc, o);
    if (lane == 0) atomicAdd(&blkcost, acc);
    __syncthreads();
    if (threadIdx.x == 0) atomicAdd(&cost[b], blkcost);
}

// ---------------------------------------------------------------------------
// Launch
// ---------------------------------------------------------------------------
extern "C" void kernel_launch(void* const* d_in, const int* in_sizes, int n_in,
                              void* d_out, int out_size) {
    const float* x = (const float*)d_in[0];
    const float* y = (const float*)d_in[1];
    float* out  = (float*)d_out;
    float* cost = out;
    float* pi   = out + NBATCH;
    float* C    = out + NBATCH + NMAT;

    cudaFuncSetAttribute(k_iter, cudaFuncAttributeMaxDynamicSharedMemorySize,
                         DYN_SMEM_BYTES);

    k_init<<<64, 256>>>(cost);
    k_cost<<<NBATCH * 32 * 32, 256>>>(x, y, C);
    for (int it = 0; it < MAX_IT; it++) {
        k_iter<<<NBATCH * RBLK, 256, DYN_SMEM_BYTES>>>(C, it);
        k_vredA<<<512, 256>>>(it);
        k_vredB<<<64, 256>>>(it);
    }
    k_pi<<<NROWS / 8, 256>>>(C, pi, cost);
}

// round 7
// speedup vs baseline: 1.1226x; 1.1226x over previous
#include <cuda_runtime.h>
#include <math.h>

// Problem constants
#define NBATCH 8
#define NPTS   2048
#define NFEAT  32
#define NROWS  (NBATCH * NPTS)                       // 16384
#define NMAT   ((size_t)NBATCH * NPTS * NPTS)        // 33554432
#define MAX_IT 100
#define RB     16                                    // rows per iter block
#define RBLK   (NPTS / RB)                           // 128 row-blocks per batch

// eps = 0.1 ; log2-domain scale: (1/eps) * log2(e)
#define S2   14.4269504088896341f
#define LN2  0.6931471805599453f
#define EPSV 0.1f
#define LOG_MUV (logf(1.0f / 2048.0f + 1e-8f))
#define LOG_NUV LOG_MUV
#define ERR_THRESH_SUM 0.8f

// Scratch (__device__ globals; no allocation allowed)
__device__ __align__(16) float g_u[NROWS];
__device__ __align__(16) float g_v[NROWS];
__device__ float g_err[MAX_IT];
__device__ __align__(16) float g_pm[NBATCH * RBLK * NPTS];   // 8 MB col partial max
__device__ __align__(16) float g_ps[NBATCH * RBLK * NPTS];   // 8 MB col partial sum
__device__ __align__(16) float g_pm2[NBATCH * 8 * NPTS];     // stage-2 partials
__device__ __align__(16) float g_ps2[NBATCH * 8 * NPTS];

__device__ __forceinline__ float ex2f(float x) {
    float y;
    asm("ex2.approx.ftz.f32 %0, %1;" : "=f"(y) : "f"(x));
    return y;
}
__device__ __forceinline__ float lg2f(float x) {
    float y;
    asm("lg2.approx.ftz.f32 %0, %1;" : "=f"(y) : "f"(x));
    return y;
}

// ---------------------------------------------------------------------------
// Init
// ---------------------------------------------------------------------------
__global__ void k_init(float* __restrict__ cost) {
    int t = blockIdx.x * blockDim.x + threadIdx.x;
    int n = gridDim.x * blockDim.x;
    for (int i = t; i < NROWS; i += n) {
        g_u[i] = 0.0f;
        g_v[i] = 0.0f;
    }
    if (t < MAX_IT) g_err[t] = 0.0f;
    if (t < NBATCH) cost[t] = 0.0f;
}

// Dummy no-op: aligns the ncu capture slot (4th kernel launch) onto k_iter.
__global__ void k_dummy() {}

// ---------------------------------------------------------------------------
// Cost matrix: C[b,i,j] = sum_d (x[b,i,d] - y[b,j,d])^2
// ---------------------------------------------------------------------------
__global__ void __launch_bounds__(256) k_cost(const float* __restrict__ x,
                                              const float* __restrict__ y,
                                              float* __restrict__ C) {
    __shared__ float xs[NFEAT * 65];
    __shared__ float ys[NFEAT * 65];

    int tile = blockIdx.x;          // 8192 tiles of 64x64
    int b  = tile >> 10;
    int ti = (tile >> 5) & 31;
    int tj = tile & 31;
    int tid = threadIdx.x;

    const float* xb = x + ((size_t)b * NPTS + (size_t)ti * 64) * NFEAT;
    const float* yb = y + ((size_t)b * NPTS + (size_t)tj * 64) * NFEAT;

    for (int e = tid; e < 64 * NFEAT; e += 256) {
        int row = e >> 5;
        int d   = e & 31;
        xs[d * 65 + row] = xb[e];
        ys[d * 65 + row] = yb[e];
    }
    __syncthreads();

    int ri = (tid >> 4) << 2;
    int cj = (tid & 15) << 2;

    float acc[4][4];
#pragma unroll
    for (int a = 0; a < 4; a++)
#pragma unroll
        for (int c = 0; c < 4; c++) acc[a][c] = 0.0f;

#pragma unroll
    for (int d = 0; d < NFEAT; d++) {
        float xa[4], yv[4];
#pragma unroll
        for (int a = 0; a < 4; a++) xa[a] = xs[d * 65 + ri + a];
#pragma unroll
        for (int c = 0; c < 4; c++) yv[c] = ys[d * 65 + cj + c];
#pragma unroll
        for (int a = 0; a < 4; a++)
#pragma unroll
            for (int c = 0; c < 4; c++) {
                float diff = xa[a] - yv[c];
                acc[a][c] = fmaf(diff, diff, acc[a][c]);
            }
    }

    float* Cb = C + (size_t)b * NPTS * NPTS + (size_t)(ti * 64 + ri) * NPTS + (tj * 64 + cj);
#pragma unroll
    for (int a = 0; a < 4; a++) {
        float4 o = make_float4(acc[a][0], acc[a][1], acc[a][2], acc[a][3]);
        *reinterpret_cast<float4*>(Cb + (size_t)a * NPTS) = o;
    }
}

// ---------------------------------------------------------------------------
// Fused iteration (R4 structure, chain-free phase 1).
// Block = 128 threads (4 warps), 16 rows, 4 chunks of 4 rows.
// Phase 1 (per chunk), warp w = row w:
//   pass A: t = (v - C)*S2 -> smem + exact row max (pure fmax, zero ex2)
//   pass B: s = sum ex2(t - m) from smem, 4 independent accumulators
//           (no online rescale -> no serial MUFU chain)
// Phase 2: per-column grouped (4-row) online LSE fold into (cm, cs) regs.
// Early freeze: g_err[it-1] < thresh (sticky).
// ---------------------------------------------------------------------------
__global__ void __launch_bounds__(128) k_iter(const float* __restrict__ C, int it) {
    if (it > 0 && g_err[it - 1] < ERR_THRESH_SUM) return;

    __shared__ float vS2_s[NPTS];        // 8 KB : v * S2
    __shared__ float t_s[4 * NPTS];      // 32 KB : t tile, 4 rows
    __shared__ float uS2_s[4];
    __shared__ float blkerr;

    int blk = blockIdx.x;                // 8 * 128 = 1024 blocks
    int b   = blk >> 7;
    int rb  = blk & 127;
    int tid = threadIdx.x;
    int w   = tid >> 5;
    int l   = tid & 31;

    const float4* vg  = reinterpret_cast<const float4*>(g_v + (b << 11));
    float4*       vs4 = reinterpret_cast<float4*>(vS2_s);
#pragma unroll
    for (int k = 0; k < 4; k++) {
        float4 t = vg[tid + (k << 7)];
        t.x *= S2; t.y *= S2; t.z *= S2; t.w *= S2;
        vs4[tid + (k << 7)] = t;
    }
    if (tid == 0) blkerr = 0.0f;
    __syncthreads();

    const float* Cb = C + ((size_t)b << 22) + (((size_t)rb * RB) << 11);
    int cq = (w << 7) + l;               // float4 col index; warp owns 512 cols

    float cm[16], cs[16];
#pragma unroll
    for (int q = 0; q < 16; q++) { cm[q] = -1e30f; cs[q] = 0.0f; }

    float4* ts_all = reinterpret_cast<float4*>(t_s);

#pragma unroll 1
    for (int ch = 0; ch < RB / 4; ch++) {
        // ---- phase 1, pass A: t -> smem + exact row max (no ex2) ----
        int rl = (ch << 2) + w;
        int r  = (b << 11) + rb * RB + rl;
        const float4* Cr  = reinterpret_cast<const float4*>(Cb + ((size_t)rl << 11));
        float4*       ts4 = ts_all + (w << 9);     // warp's 512-float4 row slot

        float mA = -1e30f, mB = -1e30f;
#pragma unroll
        for (int g = 0; g < 8; g++) {
            int idx = l + (g << 6);
            float4 c0 = Cr[idx];
            float4 c1 = Cr[idx + 32];
            float4 v0 = vs4[idx];
            float4 v1 = vs4[idx + 32];
            float t0 = fmaf(-S2, c0.x, v0.x);
            float t1 = fmaf(-S2, c0.y, v0.y);
            float t2 = fmaf(-S2, c0.z, v0.z);
            float t3 = fmaf(-S2, c0.w, v0.w);
            float t4 = fmaf(-S2, c1.x, v1.x);
            float t5 = fmaf(-S2, c1.y, v1.y);
            float t6 = fmaf(-S2, c1.z, v1.z);
            float t7 = fmaf(-S2, c1.w, v1.w);
            ts4[idx]      = make_float4(t0, t1, t2, t3);
            ts4[idx + 32] = make_float4(t4, t5, t6, t7);
            mA = fmaxf(mA, fmaxf(fmaxf(t0, t1), fmaxf(t2, t3)));
            mB = fmaxf(mB, fmaxf(fmaxf(t4, t5), fmaxf(t6, t7)));
        }
        float m = fmaxf(mA, mB);
#pragma unroll
        for (int o = 16; o; o >>= 1)
            m = fmaxf(m, __shfl_xor_sync(0xffffffffu, m, o));
        // m now uniform across the warp: exact row max.

        // ---- phase 1, pass B: independent exp-sums (no rescale chain) ----
        float s0 = 0.0f, s1 = 0.0f, s2 = 0.0f, s3 = 0.0f;
#pragma unroll
        for (int g = 0; g < 8; g++) {
            int idx = l + (g << 6);
            float4 a = ts4[idx];
            float4 bb = ts4[idx + 32];
            s0 += ex2f(a.x - m)  + ex2f(bb.x - m);
            s1 += ex2f(a.y - m)  + ex2f(bb.y - m);
            s2 += ex2f(a.z - m)  + ex2f(bb.z - m);
            s3 += ex2f(a.w - m)  + ex2f(bb.w - m);
        }
        float s = (s0 + s1) + (s2 + s3);
#pragma unroll
        for (int o = 16; o; o >>= 1)
            s += __shfl_xor_sync(0xffffffffu, s, o);

        if (l == 0) {
            float lse  = (m + lg2f(s)) * LN2;      // natural-log lse of (v - C)/eps
            float unew = EPSV * (LOG_MUV - lse);
            float du = fabsf(unew - g_u[r]);
            g_u[r]   = unew;
            uS2_s[w] = unew * S2;
            atomicAdd(&blkerr, du);
        }
        __syncthreads();   // t tile + uS2 ready for all warps

        // ---- phase 2: grouped 4-row online column LSE ----
        float us0 = uS2_s[0], us1 = uS2_s[1], us2 = uS2_s[2], us3 = uS2_s[3];
#pragma unroll
        for (int g = 0; g < 4; g++) {
            int idx = cq + (g << 5);
            float4 t0 = ts_all[idx];
            float4 t1 = ts_all[512 + idx];
            float4 t2 = ts_all[1024 + idx];
            float4 t3 = ts_all[1536 + idx];
#define COLUPD(q, e0, e1, e2, e3)                                              \
            {                                                                  \
                float a0 = (e0) + us0;                                         \
                float a1 = (e1) + us1;                                         \
                float a2 = (e2) + us2;                                         \
                float a3 = (e3) + us3;                                         \
                float m4 = fmaxf(fmaxf(a0, a1), fmaxf(a2, a3));                \
                float nm = fmaxf(cm[q], m4);                                   \
                cs[q] = cs[q] * ex2f(cm[q] - nm)                               \
                      + ((ex2f(a0 - nm) + ex2f(a1 - nm))                       \
                       + (ex2f(a2 - nm) + ex2f(a3 - nm)));                     \
                cm[q] = nm;                                                    \
            }
            COLUPD(4 * g + 0, t0.x, t1.x, t2.x, t3.x)
            COLUPD(4 * g + 1, t0.y, t1.y, t2.y, t3.y)
            COLUPD(4 * g + 2, t0.z, t1.z, t2.z, t3.z)
            COLUPD(4 * g + 3, t0.w, t1.w, t2.w, t3.w)
#undef COLUPD
        }
        __syncthreads();   // protect t tile before next chunk rewrites it
    }

    // write column partials (coalesced float4)
    size_t pb = ((size_t)blk) << 11;
    float4* pm4 = reinterpret_cast<float4*>(g_pm + pb);
    float4* ps4 = reinterpret_cast<float4*>(g_ps + pb);
#pragma unroll
    for (int g = 0; g < 4; g++) {
        pm4[cq + (g << 5)] = make_float4(cm[4*g], cm[4*g+1], cm[4*g+2], cm[4*g+3]);
        ps4[cq + (g << 5)] = make_float4(cs[4*g], cs[4*g+1], cs[4*g+2], cs[4*g+3]);
    }
    if (tid == 0) atomicAdd(&g_err[it], blkerr);
}

// ---------------------------------------------------------------------------
// v reduce, stage A: merge 16 partials -> 8 per column.
// ---------------------------------------------------------------------------
__global__ void __launch_bounds__(256) k_vredA(int it) {
    if (it > 0 && g_err[it - 1] < ERR_THRESH_SUM) return;
    int t   = blockIdx.x * 256 + threadIdx.x;    // 512 blocks -> 131072 threads
    int col = t & 2047;
    int pg  = (t >> 11) & 7;
    int b   = t >> 14;
    size_t base = (((size_t)(b * RBLK + pg * 16)) << 11) + col;
    float m = -1e30f, s = 0.0f;
#pragma unroll
    for (int k = 0; k < 16; k++) {
        float mo = g_pm[base + ((size_t)k << 11)];
        float so = g_ps[base + ((size_t)k << 11)];
        float nm = fmaxf(m, mo);
        s = s * ex2f(m - nm) + so * ex2f(mo - nm);
        m = nm;
    }
    size_t o = (((size_t)(b * 8 + pg)) << 11) + col;
    g_pm2[o] = m;
    g_ps2[o] = s;
}

// ---------------------------------------------------------------------------
// v reduce, stage B: merge 8 -> v_new = v_old + eps*(log_nu - lse).
// ---------------------------------------------------------------------------
__global__ void __launch_bounds__(256) k_vredB(int it) {
    if (it > 0 && g_err[it - 1] < ERR_THRESH_SUM) return;
    int t   = blockIdx.x * 256 + threadIdx.x;    // 64 blocks -> 16384 threads
    int col = t & 2047;
    int b   = t >> 11;
    size_t base = (((size_t)(b * 8)) << 11) + col;
    float m = -1e30f, s = 0.0f;
#pragma unroll
    for (int k = 0; k < 8; k++) {
        float mo = g_pm2[base + ((size_t)k << 11)];
        float so = g_ps2[base + ((size_t)k << 11)];
        float nm = fmaxf(m, mo);
        s = s * ex2f(m - nm) + so * ex2f(mo - nm);
        m = nm;
    }
    int j = (b << 11) + col;
    // a-domain included v, so: v_new = v_old + eps*(log_nu - lse)
    g_v[j] = g_v[j] + EPSV * (LOG_NUV - (m + lg2f(s)) * LN2);
}

// ---------------------------------------------------------------------------
// Epilogue: pi = exp((u_i + v_j - C_ij)/eps), cost[b] = sum pi*C
// ---------------------------------------------------------------------------
__global__ void __launch_bounds__(256) k_pi(const float* __restrict__ C,
                                            float* __restrict__ pi,
                                            float* __restrict__ cost) {
    __shared__ float blkcost;
    if (threadIdx.x == 0) blkcost = 0.0f;
    __syncthreads();

    int warp = (blockIdx.x << 3) + (threadIdx.x >> 5);
    int lane = threadIdx.x & 31;
    int r = warp;
    int b = r >> 11;

    float u = g_u[r];
    const float4* Cr = reinterpret_cast<const float4*>(C + (size_t)r * NPTS);
    const float4* Vr = reinterpret_cast<const float4*>(g_v + (b << 11));
    float4* Pr = reinterpret_cast<float4*>(pi + (size_t)r * NPTS);

    float acc = 0.0f;
#pragma unroll 4
    for (int k = lane; k < NPTS / 4; k += 32) {
        float4 c = Cr[k];
        float4 v = Vr[k];
        float4 p;
        p.x = ex2f((u + v.x - c.x) * S2);
        p.y = ex2f((u + v.y - c.y) * S2);
        p.z = ex2f((u + v.z - c.z) * S2);
        p.w = ex2f((u + v.w - c.w) * S2);
        Pr[k] = p;
        acc += p.x * c.x + p.y * c.y + p.z * c.z + p.w * c.w;
    }
#pragma unroll
    for (int o = 16; o; o >>= 1) acc += __shfl_xor_sync(0xffffffffu, acc, o);
    if (lane == 0) atomicAdd(&blkcost, acc);
    __syncthreads();
    if (threadIdx.x == 0) atomicAdd(&cost[b], blkcost);
}

// ---------------------------------------------------------------------------
// Launch: init -> cost -> dummy (profiling alignment) -> 100 x (iter, vredA,
// vredB) -> pi. Output layout: cost[8] | pi | C.
// ---------------------------------------------------------------------------
extern "C" void kernel_launch(void* const* d_in, const int* in_sizes, int n_in,
                              void* d_out, int out_size) {
    const float* x = (const float*)d_in[0];
    const float* y = (const float*)d_in[1];
    float* out  = (float*)d_out;
    float* cost = out;
    float* pi   = out + NBATCH;
    float* C    = out + NBATCH + NMAT;

    k_init<<<64, 256>>>(cost);
    k_cost<<<NBATCH * 32 * 32, 256>>>(x, y, C);
    k_dummy<<<1, 32>>>();   // aligns ncu capture slot onto k_iter(it=0)
    for (int it = 0; it < MAX_IT; it++) {
        k_iter<<<NBATCH * RBLK, 128>>>(C, it);
        k_vredA<<<512, 256>>>(it);
        k_vredB<<<64, 256>>>(it);
    }
    k_pi<<<NROWS / 8, 256>>>(C, pi, cost);
}

// round 8
// speedup vs baseline: 1.9885x; 1.7713x over previous
#include <cuda_runtime.h>
#include <math.h>

// Problem constants
#define NBATCH 8
#define NPTS   2048
#define NFEAT  32
#define NROWS  (NBATCH * NPTS)                       // 16384
#define NMAT   ((size_t)NBATCH * NPTS * NPTS)        // 33554432
#define MAX_IT 100

// eps = 0.1 ; log2-domain scale: (1/eps) * log2(e)
#define S2   14.4269504088896341f
#define LN2  0.6931471805599453f
#define EPSV 0.1f
#define LOG_MUV (logf(1.0f / 2048.0f + 1e-8f))      // == log_nu (N == M)
#define ERR_THRESH_SUM 0.8f

// Scratch (__device__ globals; no allocation allowed)
__device__ __align__(16) float g_u[NROWS];
__device__ __align__(16) float g_v[NROWS];
__device__ float g_err[MAX_IT];
__device__ __align__(16) float g_ct[NMAT];           // 128 MB transposed cost

__device__ __forceinline__ float ex2f(float x) {
    float y;
    asm("ex2.approx.ftz.f32 %0, %1;" : "=f"(y) : "f"(x));
    return y;
}
__device__ __forceinline__ float lg2f(float x) {
    float y;
    asm("lg2.approx.ftz.f32 %0, %1;" : "=f"(y) : "f"(x));
    return y;
}

// ---------------------------------------------------------------------------
// Init
// ---------------------------------------------------------------------------
__global__ void k_init(float* __restrict__ cost) {
    int t = blockIdx.x * blockDim.x + threadIdx.x;
    int n = gridDim.x * blockDim.x;
    for (int i = t; i < NROWS; i += n) {
        g_u[i] = 0.0f;
        g_v[i] = 0.0f;
    }
    if (t < MAX_IT) g_err[t] = 0.0f;
    if (t < NBATCH) cost[t] = 0.0f;
}

// Dummy no-op: aligns the ncu capture slot (4th kernel launch) onto the u-sweep.
__global__ void k_dummy() {}

// ---------------------------------------------------------------------------
// Cost matrix: C[b,i,j] = sum_d (x[b,i,d] - y[b,j,d])^2 ; also writes CT = C^T.
// ---------------------------------------------------------------------------
__global__ void __launch_bounds__(256) k_cost(const float* __restrict__ x,
                                              const float* __restrict__ y,
                                              float* __restrict__ C) {
    __shared__ float xs[NFEAT * 65];
    __shared__ float ys[NFEAT * 65];

    int tile = blockIdx.x;          // 8192 tiles of 64x64
    int b  = tile >> 10;
    int ti = (tile >> 5) & 31;
    int tj = tile & 31;
    int tid = threadIdx.x;

    const float* xb = x + ((size_t)b * NPTS + (size_t)ti * 64) * NFEAT;
    const float* yb = y + ((size_t)b * NPTS + (size_t)tj * 64) * NFEAT;

    for (int e = tid; e < 64 * NFEAT; e += 256) {
        int row = e >> 5;
        int d   = e & 31;
        xs[d * 65 + row] = xb[e];
        ys[d * 65 + row] = yb[e];
    }
    __syncthreads();

    int ri = (tid >> 4) << 2;
    int cj = (tid & 15) << 2;

    float acc[4][4];
#pragma unroll
    for (int a = 0; a < 4; a++)
#pragma unroll
        for (int c = 0; c < 4; c++) acc[a][c] = 0.0f;

#pragma unroll
    for (int d = 0; d < NFEAT; d++) {
        float xa[4], yv[4];
#pragma unroll
        for (int a = 0; a < 4; a++) xa[a] = xs[d * 65 + ri + a];
#pragma unroll
        for (int c = 0; c < 4; c++) yv[c] = ys[d * 65 + cj + c];
#pragma unroll
        for (int a = 0; a < 4; a++)
#pragma unroll
            for (int c = 0; c < 4; c++) {
                float diff = xa[a] - yv[c];
                acc[a][c] = fmaf(diff, diff, acc[a][c]);
            }
    }

    float* Cb = C + (size_t)b * NPTS * NPTS + (size_t)(ti * 64 + ri) * NPTS + (tj * 64 + cj);
#pragma unroll
    for (int a = 0; a < 4; a++) {
        float4 o = make_float4(acc[a][0], acc[a][1], acc[a][2], acc[a][3]);
        *reinterpret_cast<float4*>(Cb + (size_t)a * NPTS) = o;
    }

    // transposed copy: CT[b, j, i] = C[b, i, j]
    float* Tb = g_ct + (size_t)b * NPTS * NPTS + (size_t)(tj * 64 + cj) * NPTS + (ti * 64 + ri);
#pragma unroll
    for (int c = 0; c < 4; c++) {
        float4 o = make_float4(acc[0][c], acc[1][c], acc[2][c], acc[3][c]);
        *reinterpret_cast<float4*>(Tb + (size_t)c * NPTS) = o;
    }
}

// ---------------------------------------------------------------------------
// One Sinkhorn half-step (generic over u/v by pointer swap):
//   mine[r] = eps * (log_mu - lse_j((oth[j] - M[r, j]) / eps))
// M is row-major for this sweep (C for the u-pass, CT for the v-pass).
// Block = 256 threads (8 warps), warp per row, 8 rows per block, no hot syncs.
// Dual independent online-LSE chains for MUFU ILP; grouped 8-wide ex2.
// track_err != 0: accumulate sum |mine_new - mine_old| into g_err[it].
// Early freeze: g_err[it-1] < thresh (sticky; frozen iters leave g_err = 0).
// ---------------------------------------------------------------------------
__global__ void __launch_bounds__(256) k_sweep(const float* __restrict__ M,
                                               const float* __restrict__ oth,
                                               float* __restrict__ mine,
                                               int it, int track_err) {
    if (it > 0 && g_err[it - 1] < ERR_THRESH_SUM) return;

    __shared__ float oS2[NPTS];          // 8 KB : other potential * S2
    __shared__ float blkerr;

    int blk = blockIdx.x;                // 2048 blocks, 8 rows each
    int b   = blk >> 8;
    int tid = threadIdx.x;
    int w   = tid >> 5;
    int l   = tid & 31;

    const float4* og  = reinterpret_cast<const float4*>(oth + (b << 11));
    float4*       os4 = reinterpret_cast<float4*>(oS2);
#pragma unroll
    for (int k = 0; k < 2; k++) {
        float4 t = og[tid + (k << 8)];
        t.x *= S2; t.y *= S2; t.z *= S2; t.w *= S2;
        os4[tid + (k << 8)] = t;
    }
    if (tid == 0) blkerr = 0.0f;
    __syncthreads();

    int r = (blk << 3) + w;              // global row index
    const float4* Mr = reinterpret_cast<const float4*>(M + ((size_t)r << 11));

    float m0 = -1e30f, s0 = 0.0f, m1 = -1e30f, s1 = 0.0f;
#pragma unroll
    for (int g = 0; g < 8; g++) {
        int idx = l + (g << 6);
        float4 c0 = Mr[idx];
        float4 c1 = Mr[idx + 32];
        float4 v0 = os4[idx];
        float4 v1 = os4[idx + 32];
        float t0 = fmaf(-S2, c0.x, v0.x);
        float t1 = fmaf(-S2, c0.y, v0.y);
        float t2 = fmaf(-S2, c0.z, v0.z);
        float t3 = fmaf(-S2, c0.w, v0.w);
        float t4 = fmaf(-S2, c1.x, v1.x);
        float t5 = fmaf(-S2, c1.y, v1.y);
        float t6 = fmaf(-S2, c1.z, v1.z);
        float t7 = fmaf(-S2, c1.w, v1.w);
        // chain 0 handles the first 4, chain 1 the second 4 (independent)
        float mA = fmaxf(fmaxf(t0, t1), fmaxf(t2, t3));
        float n0 = fmaxf(m0, mA);
        s0 = s0 * ex2f(m0 - n0)
           + ((ex2f(t0 - n0) + ex2f(t1 - n0)) + (ex2f(t2 - n0) + ex2f(t3 - n0)));
        m0 = n0;
        float mB = fmaxf(fmaxf(t4, t5), fmaxf(t6, t7));
        float n1 = fmaxf(m1, mB);
        s1 = s1 * ex2f(m1 - n1)
           + ((ex2f(t4 - n1) + ex2f(t5 - n1)) + (ex2f(t6 - n1) + ex2f(t7 - n1)));
        m1 = n1;
    }
    float m = fmaxf(m0, m1);
    float s = s0 * ex2f(m0 - m) + s1 * ex2f(m1 - m);
#pragma unroll
    for (int o = 16; o; o >>= 1) {
        float mo = __shfl_xor_sync(0xffffffffu, m, o);
        float so = __shfl_xor_sync(0xffffffffu, s, o);
        float nm = fmaxf(m, mo);
        s = s * ex2f(m - nm) + so * ex2f(mo - nm);
        m = nm;
    }
    if (l == 0) {
        float lse  = (m + lg2f(s)) * LN2;          // natural-log lse
        float pnew = EPSV * (LOG_MUV - lse);
        if (track_err) {
            float du = fabsf(pnew - mine[r]);
            atomicAdd(&blkerr, du);
        }
        mine[r] = pnew;
    }
    if (track_err) {
        __syncthreads();
        if (tid == 0) atomicAdd(&g_err[it], blkerr);
    }
}

// ---------------------------------------------------------------------------
// Epilogue: pi = exp((u_i + v_j - C_ij)/eps), cost[b] = sum pi*C
// ---------------------------------------------------------------------------
__global__ void __launch_bounds__(256) k_pi(const float* __restrict__ C,
                                            float* __restrict__ pi,
                                            float* __restrict__ cost) {
    __shared__ float blkcost;
    if (threadIdx.x == 0) blkcost = 0.0f;
    __syncthreads();

    int warp = (blockIdx.x << 3) + (threadIdx.x >> 5);
    int lane = threadIdx.x & 31;
    int r = warp;
    int b = r >> 11;

    float u = g_u[r];
    const float4* Cr = reinterpret_cast<const float4*>(C + (size_t)r * NPTS);
    const float4* Vr = reinterpret_cast<const float4*>(g_v + (b << 11));
    float4* Pr = reinterpret_cast<float4*>(pi + (size_t)r * NPTS);

    float acc = 0.0f;
#pragma unroll 4
    for (int k = lane; k < NPTS / 4; k += 32) {
        float4 c = Cr[k];
        float4 v = Vr[k];
        float4 p;
        p.x = ex2f((u + v.x - c.x) * S2);
        p.y = ex2f((u + v.y - c.y) * S2);
        p.z = ex2f((u + v.z - c.z) * S2);
        p.w = ex2f((u + v.w - c.w) * S2);
        Pr[k] = p;
        acc += p.x * c.x + p.y * c.y + p.z * c.z + p.w * c.w;
    }
#pragma unroll
    for (int o = 16; o; o >>= 1) acc += __shfl_xor_sync(0xffffffffu, acc, o);
    if (lane == 0) atomicAdd(&blkcost, acc);
    __syncthreads();
    if (threadIdx.x == 0) atomicAdd(&cost[b], blkcost);
}

// ---------------------------------------------------------------------------
// Launch: init -> cost(+CT) -> dummy -> 100 x (u-sweep over C, v-sweep over CT)
// -> pi. Output layout (tuple order): cost[8] | pi | C.
// ---------------------------------------------------------------------------
extern "C" void kernel_launch(void* const* d_in, const int* in_sizes, int n_in,
                              void* d_out, int out_size) {
    const float* x = (const float*)d_in[0];
    const float* y = (const float*)d_in[1];
    float* out  = (float*)d_out;
    float* cost = out;
    float* pi   = out + NBATCH;
    float* C    = out + NBATCH + NMAT;

    float* ct;
    cudaGetSymbolAddress((void**)&ct, g_ct);
    float* u;
    cudaGetSymbolAddress((void**)&u, g_u);
    float* v;
    cudaGetSymbolAddress((void**)&v, g_v);

    k_init<<<64, 256>>>(cost);
    k_cost<<<NBATCH * 32 * 32, 256>>>(x, y, C);
    k_dummy<<<1, 32>>>();   // aligns ncu capture slot onto the first u-sweep
    for (int it = 0; it < MAX_IT; it++) {
        k_sweep<<<NROWS / 8, 256>>>(C,  v, u, it, 1);   // u update (tracks err)
        k_sweep<<<NROWS / 8, 256>>>(ct, u, v, it, 0);   // v update
    }
    k_pi<<<NROWS / 8, 256>>>(C, pi, cost);
}